// round 12
// baseline (speedup 1.0000x reference)
#include <cuda_runtime.h>

typedef unsigned long long u64;

#define HDIM  64
#define IDIM  8
#define KDIM  72          // 64 h + 8 x folded into one reduction
#define KK    36          // KDIM/2
#define NTHR  128
#define NPAIR 8           // batch pairs per CTA
#define NB    16          // batches per CTA

// SMEM (dynamic), per CTA (must stay <= ~113KB for 2 CTAs/SM):
//  wsm2[kk=36][j=256] float2 {w[j][2kk], w[j][2kk+1]} : 73728 B  (scalar fp32, lane-consecutive)
//  hx[2][NPAIR][KDIM] u64 (h units 0..63, x 64..71)   :  9216 B
#define WSM2_BYTES (KK * 256 * 8)
#define HX_BYTES   (2 * NPAIR * KDIM * 8)
#define SMEM_BYTES (WSM2_BYTES + HX_BYTES)

// ---- packed f32x2 helpers (Blackwell sm_100a) ----
__device__ __forceinline__ u64 ffma2(u64 a, u64 b, u64 c) {
    u64 r;
    asm("fma.rn.f32x2 %0, %1, %2, %3;" : "=l"(r) : "l"(a), "l"(b), "l"(c));
    return r;
}
__device__ __forceinline__ u64 pack2(float x, float y) {
    u64 r;
    asm("mov.b64 %0, {%1, %2};" : "=l"(r) : "f"(x), "f"(y));
    return r;
}
__device__ __forceinline__ void unpack2(u64 v, float& lo, float& hi) {
    asm("mov.b64 {%0, %1}, %2;" : "=f"(lo), "=f"(hi) : "l"(v));
}

// ---- activations: __expf is MUFU-based, ~1e-7 rel err ----
__device__ __forceinline__ float sigm_f(float x) {
    return 1.0f / (1.0f + __expf(-x));
}
__device__ __forceinline__ float tanh_f(float x) {
    return fmaf(2.0f, 1.0f / (1.0f + __expf(-2.0f * x)), -1.0f);
}

__global__ void __launch_bounds__(NTHR, 2) lstm_persistent_kernel(
    const float* __restrict__ x,      // [B, T, I]
    const float* __restrict__ Wih,    // [4H, I]
    const float* __restrict__ Whh,    // [4H, H]
    const float* __restrict__ bih,    // [4H]
    const float* __restrict__ bhh,    // [4H]
    const float* __restrict__ Wfc,    // [1, H]
    const float* __restrict__ bfc,    // [1]
    float* __restrict__ out,          // [B, 1]
    int B, int T)
{
    extern __shared__ __align__(16) char smem_raw[];
    float2* wsm2 = (float2*)smem_raw;                 // [kk*256 + j]
    u64*    hxb  = (u64*)(smem_raw + WSM2_BYTES);     // [buf][pair][KDIM]

    const int tid = threadIdx.x;
    const int u   = tid & 63;         // hidden unit (lanes consecutive within warp)
    const int q   = tid >> 6;         // pair group 0/1 (warp-uniform)
    const int pb  = q * 4;            // first pair of this thread
    const int b0  = blockIdx.x * NB;
    const int nb  = min(NB, B - b0);
    const int nx  = nb * IDIM;        // = 128 for full CTAs

    // ---- stage combined W = [Whh | Wih] as scalar float2 per (kk, row) ----
    for (int idx = tid; idx < KK * 256; idx += NTHR) {
        const int kk = idx >> 8, j = idx & 255;
        const int k0 = 2 * kk, k1 = 2 * kk + 1;
        float wa = (k0 < HDIM) ? Whh[j * HDIM + k0] : Wih[j * IDIM + (k0 - HDIM)];
        float wb = (k1 < HDIM) ? Whh[j * HDIM + k1] : Wih[j * IDIM + (k1 - HDIM)];
        wsm2[idx] = make_float2(wa, wb);
    }

    // ---- per-thread biases for gate rows u, u+64, u+128, u+192 ----
    u64 bias2[4];
#pragma unroll
    for (int g = 0; g < 4; ++g) {
        float b = bih[u + 64 * g] + bhh[u + 64 * g];
        bias2[g] = pack2(b, b);
    }

    // ---- zero hx (both buffers) ----
    for (int idx = tid; idx < 2 * NPAIR * KDIM; idx += NTHR) hxb[idx] = 0ull;

    // ---- cell state in registers ----
    float ce[4], co[4];
#pragma unroll
    for (int p = 0; p < 4; ++p) { ce[p] = 0.0f; co[p] = 0.0f; }

    // ---- load x(t=0): 128 threads == 16 batches x 8 features ----
    int xp = 0, xe = 0, xi = 0;
    if (tid < nx) {
        xp = tid >> 4;            // pair 0..7
        xe = (tid >> 3) & 1;      // half within pair
        xi = tid & 7;             // feature
        float v = x[((size_t)(b0 + 2 * xp + xe) * T) * IDIM + xi];
        ((float*)&hxb[xp * KDIM + HDIM + xi])[xe] = v;
    }
    __syncthreads();

    // ---- ANTI-PHASE STAGGER: odd CTAs delay ~3200 cyc (one-time) so the two
    //      co-resident CTAs interleave matvec (FMA) with pointwise (MUFU)
    //      instead of convoying through the same phase together. ----
    if (blockIdx.x & 1) {
        float d = (float)(tid + 1) * 1e-20f;
#pragma unroll 1
        for (int i = 0; i < 800; ++i)
            d = fmaf(d, 0.9999999f, 1e-30f);      // dependent chain, lat 4 -> ~3200 cyc
        if (d > 1e35f) out[0] = d;                // never true (d stays ~1e-18); keeps chain live
    }

    for (int t = 0; t < T; ++t) {
        // prefetch x(t+1)
        float xn = 0.0f;
        const bool do_x = (t + 1 < T) && (tid < nx);
        if (do_x)
            xn = x[((size_t)(b0 + 2 * xp + xe) * T + (t + 1)) * IDIM + xi];

        const u64* hcur = hxb + (t & 1) * (NPAIR * KDIM);
        u64*       hnxt = hxb + ((t + 1) & 1) * (NPAIR * KDIM);

        // ---- matvec over KDIM=72: 16 independent chains ----
        u64 acc[4][4];
#pragma unroll
        for (int g = 0; g < 4; ++g)
#pragma unroll
            for (int p = 0; p < 4; ++p)
                acc[g][p] = bias2[g];

#pragma unroll
        for (int kk = 0; kk < KK; ++kk) {
            // weights: 4 LDS.64, lane-consecutive (2 phases each); pack on ALU pipe
            float2 wf[4];
#pragma unroll
            for (int g = 0; g < 4; ++g)
                wf[g] = wsm2[kk * 256 + u + 64 * g];
            u64 wA[4], wB[4];
#pragma unroll
            for (int g = 0; g < 4; ++g) {
                wA[g] = pack2(wf[g].x, wf[g].x);
                wB[g] = pack2(wf[g].y, wf[g].y);
            }
            // h: 4 LDS.128 broadcast (1 phase each)
            ulonglong2 hv[4];
#pragma unroll
            for (int p = 0; p < 4; ++p)
                hv[p] = *(const ulonglong2*)(hcur + (pb + p) * KDIM + 2 * kk);
#pragma unroll
            for (int p = 0; p < 4; ++p) {
#pragma unroll
                for (int g = 0; g < 4; ++g) {
                    u64 a = acc[g][p];
                    a = ffma2(hv[p].x, wA[g], a);
                    a = ffma2(hv[p].y, wB[g], a);
                    acc[g][p] = a;
                }
            }
        }

        // stash prefetched x into next buffer (read after barrier)
        if (do_x)
            ((float*)&hnxt[xp * KDIM + HDIM + xi])[xe] = xn;

        // ---- pointwise IN REGISTERS: i,f,g,o -> c,h ----
#pragma unroll
        for (int p = 0; p < 4; ++p) {
            float gie, gio, gfe, gfo, gge, ggo, goe, goo;
            unpack2(acc[0][p], gie, gio);
            unpack2(acc[1][p], gfe, gfo);
            unpack2(acc[2][p], gge, ggo);
            unpack2(acc[3][p], goe, goo);

            float iv = sigm_f(gie);
            float fv = sigm_f(gfe);
            float gv = tanh_f(gge);
            float ov = sigm_f(goe);
            float c  = fmaf(fv, ce[p], iv * gv);
            ce[p] = c;
            float he = ov * tanh_f(c);

            iv = sigm_f(gio);
            fv = sigm_f(gfo);
            gv = tanh_f(ggo);
            ov = sigm_f(goo);
            c  = fmaf(fv, co[p], iv * gv);
            co[p] = c;
            float ho = ov * tanh_f(c);

            hnxt[(pb + p) * KDIM + u] = pack2(he, ho);
        }
        __syncthreads();   // single barrier per step
    }

    // ---- final FC: out[b] = h_T . Wfc + bfc ----
    const u64* hfin = hxb + (T & 1) * (NPAIR * KDIM);
    if (tid < nb) {
        const int p = tid >> 1, e = tid & 1;
        float s = bfc[0];
#pragma unroll
        for (int k = 0; k < HDIM; ++k)
            s = fmaf(((const float*)&hfin[p * KDIM + k])[e], Wfc[k], s);
        out[b0 + tid] = s;
    }
}

extern "C" void kernel_launch(void* const* d_in, const int* in_sizes, int n_in,
                              void* d_out, int out_size) {
    const float* x    = (const float*)d_in[0];
    const float* Wih  = (const float*)d_in[1];
    const float* Whh  = (const float*)d_in[2];
    const float* bih  = (const float*)d_in[3];
    const float* bhh  = (const float*)d_in[4];
    const float* Wfc  = (const float*)d_in[5];
    const float* bfc  = (const float*)d_in[6];
    float* out = (float*)d_out;

    const int B = out_size;                   // O = 1
    const int T = in_sizes[0] / (B * IDIM);

    cudaFuncSetAttribute(lstm_persistent_kernel,
                         cudaFuncAttributeMaxDynamicSharedMemorySize, SMEM_BYTES);

    const int grid = (B + NB - 1) / NB;       // 256 CTAs -> 2 per SM (most SMs)
    lstm_persistent_kernel<<<grid, NTHR, SMEM_BYTES>>>(x, Wih, Whh, bih, bhh, Wfc, bfc, out, B, T);
}

// round 14
// speedup vs baseline: 1.3214x; 1.3214x over previous
#include <cuda_runtime.h>

typedef unsigned long long u64;

#define HDIM  64
#define IDIM  8
#define KDIM  72          // 64 h + 8 x folded into one reduction
#define KK    36          // KDIM/2
#define NTHR  256
#define NPAIR 8           // batch pairs per CTA
#define NB    16          // batches per CTA
#define PPT   2           // pairs per thread

// SMEM (dynamic), per CTA (<= ~113KB so 2 CTAs/SM fit):
//  wsm2[kk=36][j=256] float2 {w[j][2kk], w[j][2kk+1]} : 73728 B
//  hx[2][NPAIR][KDIM] u64 (h units 0..63, x 64..71)   :  9216 B
#define WSM2_BYTES (KK * 256 * 8)
#define HX_BYTES   (2 * NPAIR * KDIM * 8)
#define SMEM_BYTES (WSM2_BYTES + HX_BYTES)

// ---- packed f32x2 helpers (Blackwell sm_100a) ----
__device__ __forceinline__ u64 ffma2(u64 a, u64 b, u64 c) {
    u64 r;
    asm("fma.rn.f32x2 %0, %1, %2, %3;" : "=l"(r) : "l"(a), "l"(b), "l"(c));
    return r;
}
__device__ __forceinline__ u64 pack2(float x, float y) {
    u64 r;
    asm("mov.b64 %0, {%1, %2};" : "=l"(r) : "f"(x), "f"(y));
    return r;
}
__device__ __forceinline__ void unpack2(u64 v, float& lo, float& hi) {
    asm("mov.b64 {%0, %1}, %2;" : "=f"(lo), "=f"(hi) : "l"(v));
}

// ---- activations: MUFU ex2 + MUFU rcp (no FDIV Newton chain); ~2 ulp ----
__device__ __forceinline__ float sigm_f(float x) {
    return __fdividef(1.0f, 1.0f + __expf(-x));
}
__device__ __forceinline__ float tanh_f(float x) {
    return fmaf(2.0f, __fdividef(1.0f, 1.0f + __expf(-2.0f * x)), -1.0f);
}

__global__ void __launch_bounds__(NTHR, 2) lstm_persistent_kernel(
    const float* __restrict__ x,      // [B, T, I]
    const float* __restrict__ Wih,    // [4H, I]
    const float* __restrict__ Whh,    // [4H, H]
    const float* __restrict__ bih,    // [4H]
    const float* __restrict__ bhh,    // [4H]
    const float* __restrict__ Wfc,    // [1, H]
    const float* __restrict__ bfc,    // [1]
    float* __restrict__ out,          // [B, 1]
    int B, int T)
{
    extern __shared__ __align__(16) char smem_raw[];
    float2* wsm2 = (float2*)smem_raw;                 // [kk*256 + j]
    u64*    hxb  = (u64*)(smem_raw + WSM2_BYTES);     // [buf][pair][KDIM]

    const int tid = threadIdx.x;
    const int u   = tid & 63;         // hidden unit
    const int q   = tid >> 6;         // pair group 0..3 (warp-uniform)
    const int pb  = q * PPT;          // first pair of this thread
    const int b0  = blockIdx.x * NB;
    const int nb  = min(NB, B - b0);
    const int nx  = nb * IDIM;        // = 128 for full CTAs

    // ---- stage combined W = [Whh | Wih] as scalar float2 per (kk, row) ----
    for (int idx = tid; idx < KK * 256; idx += NTHR) {
        const int kk = idx >> 8, j = idx & 255;
        const int k0 = 2 * kk, k1 = 2 * kk + 1;
        float wa = (k0 < HDIM) ? Whh[j * HDIM + k0] : Wih[j * IDIM + (k0 - HDIM)];
        float wb = (k1 < HDIM) ? Whh[j * HDIM + k1] : Wih[j * IDIM + (k1 - HDIM)];
        wsm2[idx] = make_float2(wa, wb);
    }

    // ---- per-thread biases for gate rows u, u+64, u+128, u+192 ----
    u64 bias2[4];
#pragma unroll
    for (int g = 0; g < 4; ++g) {
        float b = bih[u + 64 * g] + bhh[u + 64 * g];
        bias2[g] = pack2(b, b);
    }

    // ---- zero hx (both buffers) ----
    for (int idx = tid; idx < 2 * NPAIR * KDIM; idx += NTHR) hxb[idx] = 0ull;

    // ---- cell state in registers ----
    float ce[PPT], co[PPT];
#pragma unroll
    for (int p = 0; p < PPT; ++p) { ce[p] = 0.0f; co[p] = 0.0f; }

    // ---- load x(t=0): first 128 threads cover 16 batches x 8 features ----
    int xp = 0, xe = 0, xi = 0;
    if (tid < nx) {
        xp = tid >> 4;            // pair 0..7
        xe = (tid >> 3) & 1;      // half within pair
        xi = tid & 7;             // feature
        float v = x[((size_t)(b0 + 2 * xp + xe) * T) * IDIM + xi];
        ((float*)&hxb[xp * KDIM + HDIM + xi])[xe] = v;
    }
    __syncthreads();

    for (int t = 0; t < T; ++t) {
        // prefetch x(t+1)
        float xn = 0.0f;
        const bool do_x = (t + 1 < T) && (tid < nx);
        if (do_x)
            xn = x[((size_t)(b0 + 2 * xp + xe) * T + (t + 1)) * IDIM + xi];

        const u64* hcur = hxb + (t & 1) * (NPAIR * KDIM);
        u64*       hnxt = hxb + ((t + 1) & 1) * (NPAIR * KDIM);

        // ---- matvec over KDIM=72: 8 independent chains ----
        u64 acc[4][PPT];
#pragma unroll
        for (int g = 0; g < 4; ++g)
#pragma unroll
            for (int p = 0; p < PPT; ++p)
                acc[g][p] = bias2[g];

#pragma unroll
        for (int kk = 0; kk < KK; ++kk) {
            // weights: 4 LDS.64, lane-consecutive; pack on ALU pipe
            float2 wf[4];
#pragma unroll
            for (int g = 0; g < 4; ++g)
                wf[g] = wsm2[kk * 256 + u + 64 * g];
            u64 wA[4], wB[4];
#pragma unroll
            for (int g = 0; g < 4; ++g) {
                wA[g] = pack2(wf[g].x, wf[g].x);
                wB[g] = pack2(wf[g].y, wf[g].y);
            }
            // h: 2 LDS.128 broadcast
            ulonglong2 hv[PPT];
#pragma unroll
            for (int p = 0; p < PPT; ++p)
                hv[p] = *(const ulonglong2*)(hcur + (pb + p) * KDIM + 2 * kk);
#pragma unroll
            for (int p = 0; p < PPT; ++p) {
#pragma unroll
                for (int g = 0; g < 4; ++g) {
                    u64 a = acc[g][p];
                    a = ffma2(hv[p].x, wA[g], a);
                    a = ffma2(hv[p].y, wB[g], a);
                    acc[g][p] = a;
                }
            }
        }

        // stash prefetched x into next buffer (read after barrier)
        if (do_x)
            ((float*)&hnxt[xp * KDIM + HDIM + xi])[xe] = xn;

        // ---- pointwise IN REGISTERS: i,f,g,o -> c,h ----
#pragma unroll
        for (int p = 0; p < PPT; ++p) {
            float gie, gio, gfe, gfo, gge, ggo, goe, goo;
            unpack2(acc[0][p], gie, gio);
            unpack2(acc[1][p], gfe, gfo);
            unpack2(acc[2][p], gge, ggo);
            unpack2(acc[3][p], goe, goo);

            float iv = sigm_f(gie);
            float fv = sigm_f(gfe);
            float gv = tanh_f(gge);
            float ov = sigm_f(goe);
            float c  = fmaf(fv, ce[p], iv * gv);
            ce[p] = c;
            float he = ov * tanh_f(c);

            iv = sigm_f(gio);
            fv = sigm_f(gfo);
            gv = tanh_f(ggo);
            ov = sigm_f(goo);
            c  = fmaf(fv, co[p], iv * gv);
            co[p] = c;
            float ho = ov * tanh_f(c);

            hnxt[(pb + p) * KDIM + u] = pack2(he, ho);
        }
        __syncthreads();   // single barrier per step
    }

    // ---- final FC: out[b] = h_T . Wfc + bfc ----
    const u64* hfin = hxb + (T & 1) * (NPAIR * KDIM);
    if (tid < nb) {
        const int p = tid >> 1, e = tid & 1;
        float s = bfc[0];
#pragma unroll
        for (int k = 0; k < HDIM; ++k)
            s = fmaf(((const float*)&hfin[p * KDIM + k])[e], Wfc[k], s);
        out[b0 + tid] = s;
    }
}

extern "C" void kernel_launch(void* const* d_in, const int* in_sizes, int n_in,
                              void* d_out, int out_size) {
    const float* x    = (const float*)d_in[0];
    const float* Wih  = (const float*)d_in[1];
    const float* Whh  = (const float*)d_in[2];
    const float* bih  = (const float*)d_in[3];
    const float* bhh  = (const float*)d_in[4];
    const float* Wfc  = (const float*)d_in[5];
    const float* bfc  = (const float*)d_in[6];
    float* out = (float*)d_out;

    const int B = out_size;                   // O = 1
    const int T = in_sizes[0] / (B * IDIM);

    cudaFuncSetAttribute(lstm_persistent_kernel,
                         cudaFuncAttributeMaxDynamicSharedMemorySize, SMEM_BYTES);

    const int grid = (B + NB - 1) / NB;       // 256 CTAs -> 2 per SM (most SMs)
    lstm_persistent_kernel<<<grid, NTHR, SMEM_BYTES>>>(x, Wih, Whh, bih, bhh, Wfc, bfc, out, B, T);
}

// round 15
// speedup vs baseline: 1.4341x; 1.0852x over previous
#include <cuda_runtime.h>

typedef unsigned long long u64;

#define HDIM  64
#define IDIM  8
#define KDIM  72          // 64 h + 8 x folded into one reduction
#define KK    36          // KDIM/2
#define NTHR  256
#define NPAIR 8           // batch pairs per CTA
#define NB    16          // batches per CTA
#define PPT   2           // pairs per thread

// SMEM (dynamic), per CTA (<= ~113KB so 2 CTAs/SM fit):
//  wsm2[kk=36][j=256] float2 {w[j][2kk], w[j][2kk+1]} : 73728 B
//  hx[2][NPAIR][KDIM] u64 (h units 0..63, x 64..71)   :  9216 B
#define WSM2_BYTES (KK * 256 * 8)
#define HX_BYTES   (2 * NPAIR * KDIM * 8)
#define SMEM_BYTES (WSM2_BYTES + HX_BYTES)

// ---- packed f32x2 helpers (Blackwell sm_100a) ----
__device__ __forceinline__ u64 ffma2(u64 a, u64 b, u64 c) {
    u64 r;
    asm("fma.rn.f32x2 %0, %1, %2, %3;" : "=l"(r) : "l"(a), "l"(b), "l"(c));
    return r;
}
__device__ __forceinline__ u64 pack2(float x, float y) {
    u64 r;
    asm("mov.b64 %0, {%1, %2};" : "=l"(r) : "f"(x), "f"(y));
    return r;
}
__device__ __forceinline__ void unpack2(u64 v, float& lo, float& hi) {
    asm("mov.b64 {%0, %1}, %2;" : "=f"(lo), "=f"(hi) : "l"(v));
}

// ---- activations: MUFU ex2 + MUFU rcp; ~2 ulp ----
__device__ __forceinline__ float sigm_f(float x) {
    return __fdividef(1.0f, 1.0f + __expf(-x));
}
__device__ __forceinline__ float tanh_f(float x) {
    return fmaf(2.0f, __fdividef(1.0f, 1.0f + __expf(-2.0f * x)), -1.0f);
}

__global__ void __launch_bounds__(NTHR, 2) lstm_persistent_kernel(
    const float* __restrict__ x,      // [B, T, I]
    const float* __restrict__ Wih,    // [4H, I]
    const float* __restrict__ Whh,    // [4H, H]
    const float* __restrict__ bih,    // [4H]
    const float* __restrict__ bhh,    // [4H]
    const float* __restrict__ Wfc,    // [1, H]
    const float* __restrict__ bfc,    // [1]
    float* __restrict__ out,          // [B, 1]
    int B, int T)
{
    extern __shared__ __align__(16) char smem_raw[];
    float2* wsm2 = (float2*)smem_raw;                 // [kk*256 + j]
    u64*    hxb  = (u64*)(smem_raw + WSM2_BYTES);     // [buf][pair][KDIM]

    const int tid = threadIdx.x;
    const int u   = tid & 63;         // hidden unit (= local lane within group)
    const int q   = tid >> 6;         // group 0..3 (2 warps each; warp-uniform)
    const int pb  = q * PPT;          // this group's pairs: pb, pb+1
    const int b0  = blockIdx.x * NB;

    // ---- stage combined W = [Whh | Wih] as scalar float2 per (kk, row) ----
    for (int idx = tid; idx < KK * 256; idx += NTHR) {
        const int kk = idx >> 8, j = idx & 255;
        const int k0 = 2 * kk, k1 = 2 * kk + 1;
        float wa = (k0 < HDIM) ? Whh[j * HDIM + k0] : Wih[j * IDIM + (k0 - HDIM)];
        float wb = (k1 < HDIM) ? Whh[j * HDIM + k1] : Wih[j * IDIM + (k1 - HDIM)];
        wsm2[idx] = make_float2(wa, wb);
    }

    // ---- per-thread biases for gate rows u, u+64, u+128, u+192 ----
    u64 bias2[4];
#pragma unroll
    for (int g = 0; g < 4; ++g) {
        float b = bih[u + 64 * g] + bhh[u + 64 * g];
        bias2[g] = pack2(b, b);
    }

    // ---- zero hx (both buffers) ----
    for (int idx = tid; idx < 2 * NPAIR * KDIM; idx += NTHR) hxb[idx] = 0ull;

    // ---- cell state in registers ----
    float ce[PPT], co[PPT];
#pragma unroll
    for (int p = 0; p < PPT; ++p) { ce[p] = 0.0f; co[p] = 0.0f; }

    // ---- GROUP-LOCAL x staging: group q loads x only for its own pairs.
    //      This removes ALL cross-group data flow -> groups free-run on
    //      named barriers and naturally anti-phase (FMA fills MUFU gaps). ----
    const int l = u;                   // local lane 0..63
    const int po = l >> 4;             // pair offset 0..1 (valid when l < 32)
    const int xe = (l >> 3) & 1;       // half within pair
    const int xi = l & 7;              // feature
    const int xbatch = b0 + 2 * (pb + po) + xe;
    const bool xok = (l < 32) && (xbatch < B);
    if (xok) {
        float v = x[((size_t)xbatch * T) * IDIM + xi];
        ((float*)&hxb[(pb + po) * KDIM + HDIM + xi])[xe] = v;
    }
    __syncthreads();   // weights + initial state visible to all groups

    for (int t = 0; t < T; ++t) {
        // prefetch x(t+1) for own group's pairs
        float xn = 0.0f;
        const bool do_x = (t + 1 < T) && xok;
        if (do_x)
            xn = x[((size_t)xbatch * T + (t + 1)) * IDIM + xi];

        const u64* hcur = hxb + (t & 1) * (NPAIR * KDIM);
        u64*       hnxt = hxb + ((t + 1) & 1) * (NPAIR * KDIM);

        // ---- matvec over KDIM=72: 8 independent chains ----
        u64 acc[4][PPT];
#pragma unroll
        for (int g = 0; g < 4; ++g)
#pragma unroll
            for (int p = 0; p < PPT; ++p)
                acc[g][p] = bias2[g];

#pragma unroll
        for (int kk = 0; kk < KK; ++kk) {
            // weights: 4 LDS.64, lane-consecutive; pack on ALU pipe
            float2 wf[4];
#pragma unroll
            for (int g = 0; g < 4; ++g)
                wf[g] = wsm2[kk * 256 + u + 64 * g];
            u64 wA[4], wB[4];
#pragma unroll
            for (int g = 0; g < 4; ++g) {
                wA[g] = pack2(wf[g].x, wf[g].x);
                wB[g] = pack2(wf[g].y, wf[g].y);
            }
            // h: 2 LDS.128 broadcast (own pairs only)
            ulonglong2 hv[PPT];
#pragma unroll
            for (int p = 0; p < PPT; ++p)
                hv[p] = *(const ulonglong2*)(hcur + (pb + p) * KDIM + 2 * kk);
#pragma unroll
            for (int p = 0; p < PPT; ++p) {
#pragma unroll
                for (int g = 0; g < 4; ++g) {
                    u64 a = acc[g][p];
                    a = ffma2(hv[p].x, wA[g], a);
                    a = ffma2(hv[p].y, wB[g], a);
                    acc[g][p] = a;
                }
            }
        }

        // stash prefetched x into next buffer (own pairs; read after group barrier)
        if (do_x)
            ((float*)&hnxt[(pb + po) * KDIM + HDIM + xi])[xe] = xn;

        // ---- pointwise IN REGISTERS: i,f,g,o -> c,h ----
#pragma unroll
        for (int p = 0; p < PPT; ++p) {
            float gie, gio, gfe, gfo, gge, ggo, goe, goo;
            unpack2(acc[0][p], gie, gio);
            unpack2(acc[1][p], gfe, gfo);
            unpack2(acc[2][p], gge, ggo);
            unpack2(acc[3][p], goe, goo);

            float iv = sigm_f(gie);
            float fv = sigm_f(gfe);
            float gv = tanh_f(gge);
            float ov = sigm_f(goe);
            float c  = fmaf(fv, ce[p], iv * gv);
            ce[p] = c;
            float he = ov * tanh_f(c);

            iv = sigm_f(gio);
            fv = sigm_f(gfo);
            gv = tanh_f(ggo);
            ov = sigm_f(goo);
            c  = fmaf(fv, co[p], iv * gv);
            co[p] = c;
            float ho = ov * tanh_f(c);

            hnxt[(pb + p) * KDIM + u] = pack2(he, ho);
        }

        // ---- GROUP barrier only (2 warps): groups free-run vs each other ----
        asm volatile("bar.sync %0, %1;" :: "r"(1 + q), "r"(64) : "memory");
    }

    __syncthreads();   // FC below reads h across groups

    // ---- final FC: out[b] = h_T . Wfc + bfc ----
    const u64* hfin = hxb + (T & 1) * (NPAIR * KDIM);
    const int nb = min(NB, B - b0);
    if (tid < nb) {
        const int p = tid >> 1, e = tid & 1;
        float s = bfc[0];
#pragma unroll
        for (int k = 0; k < HDIM; ++k)
            s = fmaf(((const float*)&hfin[p * KDIM + k])[e], Wfc[k], s);
        out[b0 + tid] = s;
    }
}

extern "C" void kernel_launch(void* const* d_in, const int* in_sizes, int n_in,
                              void* d_out, int out_size) {
    const float* x    = (const float*)d_in[0];
    const float* Wih  = (const float*)d_in[1];
    const float* Whh  = (const float*)d_in[2];
    const float* bih  = (const float*)d_in[3];
    const float* bhh  = (const float*)d_in[4];
    const float* Wfc  = (const float*)d_in[5];
    const float* bfc  = (const float*)d_in[6];
    float* out = (float*)d_out;

    const int B = out_size;                   // O = 1
    const int T = in_sizes[0] / (B * IDIM);

    cudaFuncSetAttribute(lstm_persistent_kernel,
                         cudaFuncAttributeMaxDynamicSharedMemorySize, SMEM_BYTES);

    const int grid = (B + NB - 1) / NB;       // 256 CTAs -> 2 per SM (most SMs)
    lstm_persistent_kernel<<<grid, NTHR, SMEM_BYTES>>>(x, Wih, Whh, bih, bhh, Wfc, bfc, out, B, T);
}